// round 9
// baseline (speedup 1.0000x reference)
#include <cuda_runtime.h>
#include <math.h>

// ---------------- problem constants (fixed shapes) ----------------
#define NNODES 50000
#define NEDGES 800000
#define IN_CH  256
#define HID    64
#define HEADS  2
#define C1     (HEADS * HID)        // 128
#define EE     (NEDGES + NNODES)    // 850000 edges incl. self loops
#define NEG_SLOPE 0.2f
#define BN_EPS    1e-5f

// ---------------- scratch (device globals; no allocations) ----------------
__device__ float g_xl1[NNODES * C1];
__device__ float g_xr1[NNODES * C1];
__device__ float g_h1 [NNODES * C1];
__device__ float g_xl2[NNODES * HID];
__device__ float g_xr2[NNODES * HID];
__device__ float g_h2 [NNODES * HID];
__device__ int   g_rowptr[NNODES + 1];
__device__ int   g_fill[NNODES];
__device__ int   g_eid[EE];

// ---------------- CSR build ----------------
__global__ void zero_rowptr() {
    int i = blockIdx.x * blockDim.x + threadIdx.x;
    if (i <= NNODES) g_rowptr[i] = 0;
}

__global__ void csr_hist(const int* __restrict__ edst, int ne, int ee) {
    int e = blockIdx.x * blockDim.x + threadIdx.x;
    if (e >= ee) return;
    int d = (e < ne) ? edst[e] : (e - ne);
    atomicAdd(&g_rowptr[d + 1], 1);
}

// single-block inclusive scan over NNODES+1 counts (rowptr[0]=0 preserved)
__global__ void csr_scan() {
    __shared__ int warpsums[32];
    __shared__ int carry;
    int tid = threadIdx.x;              // 1024 threads
    int lane = tid & 31, wid = tid >> 5;
    if (tid == 0) carry = 0;
    __syncthreads();
    for (int base = 0; base <= NNODES; base += 1024) {
        int idx = base + tid;
        int v = (idx <= NNODES) ? g_rowptr[idx] : 0;
        int x = v;
        #pragma unroll
        for (int o = 1; o < 32; o <<= 1) {
            int y = __shfl_up_sync(0xFFFFFFFFu, x, o);
            if (lane >= o) x += y;
        }
        if (lane == 31) warpsums[wid] = x;
        __syncthreads();
        if (wid == 0) {
            int w = warpsums[lane];
            #pragma unroll
            for (int o = 1; o < 32; o <<= 1) {
                int y = __shfl_up_sync(0xFFFFFFFFu, w, o);
                if (lane >= o) w += y;
            }
            warpsums[lane] = w;
        }
        __syncthreads();
        int incl = x + (wid > 0 ? warpsums[wid - 1] : 0) + carry;
        if (idx <= NNODES) g_rowptr[idx] = incl;
        __syncthreads();
        if (tid == 1023) carry = incl;
        __syncthreads();
    }
}

__global__ void csr_copy_fill() {
    int i = blockIdx.x * blockDim.x + threadIdx.x;
    if (i < NNODES) g_fill[i] = g_rowptr[i];
}

__global__ void csr_scatter(const int* __restrict__ esrc, const int* __restrict__ edst,
                            int ne, int ee) {
    int e = blockIdx.x * blockDim.x + threadIdx.x;
    if (e >= ee) return;
    int s, d;
    if (e < ne) { s = esrc[e]; d = edst[e]; }
    else        { s = e - ne; d = s; }
    int pos = atomicAdd(&g_fill[d], 1);
    g_eid[pos] = s;
}

// ---------------- tiled SGEMM with bias: C[M,N] = A[M,K]@B[K,N] + bias ----------------
__device__ __forceinline__ float* scr(int id) {
    switch (id) {
        case 0: return g_xl1;
        case 1: return g_xr1;
        case 2: return g_h1;
        case 3: return g_xl2;
        case 4: return g_xr2;
    }
    return nullptr;
}

__global__ void sgemm_bias(const float* __restrict__ Aext, int aId,
                           const float* __restrict__ B,
                           const float* __restrict__ bias,
                           int cId, int M, int K, int N) {
    const float* A = (aId >= 0) ? scr(aId) : Aext;
    float* C = scr(cId);

    __shared__ float As[16][64];   // [k][row]
    __shared__ float Bs[16][64];   // [k][col]

    int tid = threadIdx.x;                // 256 threads
    int tx = tid % 16, ty = tid / 16;     // 16x16 thread tile, each does 4x4
    int rowBase = blockIdx.y * 64;
    int colBase = blockIdx.x * 64;

    float acc[4][4] = {};
    for (int k0 = 0; k0 < K; k0 += 16) {
        #pragma unroll
        for (int i = 0; i < 4; i++) {
            int lin = tid + i * 256;          // 0..1023
            int r  = lin >> 4, kk = lin & 15; // A tile 64x16
            int grow = rowBase + r;
            As[kk][r] = (grow < M) ? A[(size_t)grow * K + k0 + kk] : 0.f;
            int kb = lin >> 6, cb = lin & 63; // B tile 16x64
            int gcol = colBase + cb;
            Bs[kb][cb] = (gcol < N) ? B[(size_t)(k0 + kb) * N + gcol] : 0.f;
        }
        __syncthreads();
        #pragma unroll
        for (int kk = 0; kk < 16; kk++) {
            float ra[4], rb[4];
            #pragma unroll
            for (int i = 0; i < 4; i++) ra[i] = As[kk][ty * 4 + i];
            #pragma unroll
            for (int j = 0; j < 4; j++) rb[j] = Bs[kk][tx * 4 + j];
            #pragma unroll
            for (int i = 0; i < 4; i++)
                #pragma unroll
                for (int j = 0; j < 4; j++) acc[i][j] += ra[i] * rb[j];
        }
        __syncthreads();
    }
    #pragma unroll
    for (int i = 0; i < 4; i++) {
        int grow = rowBase + ty * 4 + i;
        if (grow >= M) continue;
        #pragma unroll
        for (int j = 0; j < 4; j++) {
            int gcol = colBase + tx * 4 + j;
            if (gcol < N) C[(size_t)grow * N + gcol] = acc[i][j] + bias[gcol];
        }
    }
}

// ---------------- layer 1 fused: online softmax + aggregation + bias + BN + ELU ----
// one warp per destination node; lane covers channels [4*lane, 4*lane+4)
// lanes 0-15 -> head 0 (ch 0..63), lanes 16-31 -> head 1 (ch 64..127)
__global__ void gat1_fused(const float* __restrict__ att, const float* __restrict__ bias,
                           const float* __restrict__ bng, const float* __restrict__ bnb,
                           const float* __restrict__ bnm, const float* __restrict__ bnv) {
    int warp = (blockIdx.x * blockDim.x + threadIdx.x) >> 5;
    int lane = threadIdx.x & 31;
    if (warp >= NNODES) return;
    int d = warp;
    int cbase = lane * 4;

    float4 xr = *(const float4*)(g_xr1 + (size_t)d * C1 + cbase);
    float4 a4 = *(const float4*)(att + cbase);

    float4 acc = make_float4(0.f, 0.f, 0.f, 0.f);
    float m = -INFINITY, s = 0.f;

    int start = g_rowptr[d], end = g_rowptr[d + 1];
    for (int base = start; base < end; base += 32) {
        int sv = (base + lane < end) ? g_eid[base + lane] : 0;
        int nb = min(32, end - base);
        for (int j = 0; j < nb; j++) {
            int src = __shfl_sync(0xFFFFFFFFu, sv, j);
            float4 xl = *(const float4*)(g_xl1 + (size_t)src * C1 + cbase);
            float v0 = xl.x + xr.x; v0 = v0 > 0.f ? v0 : NEG_SLOPE * v0;
            float v1 = xl.y + xr.y; v1 = v1 > 0.f ? v1 : NEG_SLOPE * v1;
            float v2 = xl.z + xr.z; v2 = v2 > 0.f ? v2 : NEG_SLOPE * v2;
            float v3 = xl.w + xr.w; v3 = v3 > 0.f ? v3 : NEG_SLOPE * v3;
            float t = a4.x * v0 + a4.y * v1 + a4.z * v2 + a4.w * v3;
            // butterfly reduce within each 16-lane half (per-head logit)
            t += __shfl_xor_sync(0xFFFFFFFFu, t, 8);
            t += __shfl_xor_sync(0xFFFFFFFFu, t, 4);
            t += __shfl_xor_sync(0xFFFFFFFFu, t, 2);
            t += __shfl_xor_sync(0xFFFFFFFFu, t, 1);
            // online softmax update (per-head state, uniform within half-warp)
            float mn = fmaxf(m, t);
            float sc = __expf(m - mn);   // 0 on first edge (m = -inf)
            float p  = __expf(t - mn);
            s = s * sc + p;
            acc.x = acc.x * sc + p * xl.x;
            acc.y = acc.y * sc + p * xl.y;
            acc.z = acc.z * sc + p * xl.z;
            acc.w = acc.w * sc + p * xl.w;
            m = mn;
        }
    }

    float inv = 1.f / s;
    float4 bi = *(const float4*)(bias + cbase);
    float4 gg = *(const float4*)(bng + cbase);
    float4 bb = *(const float4*)(bnb + cbase);
    float4 mm = *(const float4*)(bnm + cbase);
    float4 vv = *(const float4*)(bnv + cbase);
    float4 o;
    o.x = (acc.x * inv + bi.x - mm.x) * rsqrtf(vv.x + BN_EPS) * gg.x + bb.x;
    o.y = (acc.y * inv + bi.y - mm.y) * rsqrtf(vv.y + BN_EPS) * gg.y + bb.y;
    o.z = (acc.z * inv + bi.z - mm.z) * rsqrtf(vv.z + BN_EPS) * gg.z + bb.z;
    o.w = (acc.w * inv + bi.w - mm.w) * rsqrtf(vv.w + BN_EPS) * gg.w + bb.w;
    o.x = o.x > 0.f ? o.x : __expf(o.x) - 1.f;
    o.y = o.y > 0.f ? o.y : __expf(o.y) - 1.f;
    o.z = o.z > 0.f ? o.z : __expf(o.z) - 1.f;
    o.w = o.w > 0.f ? o.w : __expf(o.w) - 1.f;
    *(float4*)(g_h1 + (size_t)d * C1 + cbase) = o;
}

// ---------------- layer 2 fused: 64 ch, 1 head; lane covers 2 channels ----------------
__global__ void gat2_fused(const float* __restrict__ att, const float* __restrict__ bias,
                           const float* __restrict__ bng, const float* __restrict__ bnb,
                           const float* __restrict__ bnm, const float* __restrict__ bnv) {
    int warp = (blockIdx.x * blockDim.x + threadIdx.x) >> 5;
    int lane = threadIdx.x & 31;
    if (warp >= NNODES) return;
    int d = warp;
    int cbase = lane * 2;

    float2 xr = *(const float2*)(g_xr2 + (size_t)d * HID + cbase);
    float2 a2 = *(const float2*)(att + cbase);

    float2 acc = make_float2(0.f, 0.f);
    float m = -INFINITY, s = 0.f;

    int start = g_rowptr[d], end = g_rowptr[d + 1];
    for (int base = start; base < end; base += 32) {
        int sv = (base + lane < end) ? g_eid[base + lane] : 0;
        int nb = min(32, end - base);
        for (int j = 0; j < nb; j++) {
            int src = __shfl_sync(0xFFFFFFFFu, sv, j);
            float2 xl = *(const float2*)(g_xl2 + (size_t)src * HID + cbase);
            float v0 = xl.x + xr.x; v0 = v0 > 0.f ? v0 : NEG_SLOPE * v0;
            float v1 = xl.y + xr.y; v1 = v1 > 0.f ? v1 : NEG_SLOPE * v1;
            float t = a2.x * v0 + a2.y * v1;
            #pragma unroll
            for (int o = 16; o; o >>= 1) t += __shfl_xor_sync(0xFFFFFFFFu, t, o);
            float mn = fmaxf(m, t);
            float sc = __expf(m - mn);
            float p  = __expf(t - mn);
            s = s * sc + p;
            acc.x = acc.x * sc + p * xl.x;
            acc.y = acc.y * sc + p * xl.y;
            m = mn;
        }
    }

    float inv = 1.f / s;
    float2 bi = *(const float2*)(bias + cbase);
    float2 gg = *(const float2*)(bng + cbase);
    float2 bb = *(const float2*)(bnb + cbase);
    float2 mm = *(const float2*)(bnm + cbase);
    float2 vv = *(const float2*)(bnv + cbase);
    float2 o;
    o.x = (acc.x * inv + bi.x - mm.x) * rsqrtf(vv.x + BN_EPS) * gg.x + bb.x;
    o.y = (acc.y * inv + bi.y - mm.y) * rsqrtf(vv.y + BN_EPS) * gg.y + bb.y;
    o.x = o.x > 0.f ? o.x : __expf(o.x) - 1.f;
    o.y = o.y > 0.f ? o.y : __expf(o.y) - 1.f;
    *(float2*)(g_h2 + (size_t)d * HID + cbase) = o;
}

// ---------------- classifier: sigmoid(h2 @ Wc + bc), warp per node ----------------
__global__ void classifier(const float* __restrict__ Wc, const float* __restrict__ bc,
                           float* __restrict__ out) {
    int warp = (blockIdx.x * blockDim.x + threadIdx.x) >> 5;
    int lane = threadIdx.x & 31;
    if (warp >= NNODES) return;
    const float* h = g_h2 + (size_t)warp * HID;
    float acc = h[lane] * Wc[lane] + h[lane + 32] * Wc[lane + 32];
    #pragma unroll
    for (int o = 16; o; o >>= 1) acc += __shfl_xor_sync(0xFFFFFFFFu, acc, o);
    if (lane == 0) out[warp] = 1.f / (1.f + __expf(-(acc + bc[0])));
}

// ---------------- host launcher ----------------
extern "C" void kernel_launch(void* const* d_in, const int* in_sizes, int n_in,
                              void* d_out, int out_size) {
    const float* x      = (const float*)d_in[0];
    const int*   eidx   = (const int*)d_in[1];
    const float* W1l    = (const float*)d_in[2];
    const float* b1l    = (const float*)d_in[3];
    const float* W1r    = (const float*)d_in[4];
    const float* b1r    = (const float*)d_in[5];
    const float* att1   = (const float*)d_in[6];
    const float* bias1  = (const float*)d_in[7];
    const float* bn1_g  = (const float*)d_in[8];
    const float* bn1_b  = (const float*)d_in[9];
    const float* bn1_m  = (const float*)d_in[10];
    const float* bn1_v  = (const float*)d_in[11];
    const float* W2l    = (const float*)d_in[12];
    const float* b2l    = (const float*)d_in[13];
    const float* W2r    = (const float*)d_in[14];
    const float* b2r    = (const float*)d_in[15];
    const float* att2   = (const float*)d_in[16];
    const float* bias2  = (const float*)d_in[17];
    const float* bn2_g  = (const float*)d_in[18];
    const float* bn2_b  = (const float*)d_in[19];
    const float* bn2_m  = (const float*)d_in[20];
    const float* bn2_v  = (const float*)d_in[21];
    const float* Wc     = (const float*)d_in[22];
    const float* bc     = (const float*)d_in[23];
    float* out = (float*)d_out;

    const int n  = in_sizes[0] / IN_CH;    // 50000
    const int ne = in_sizes[1] / 2;        // 800000
    const int ee = ne + n;                 // 850000
    const int* esrc = eidx;
    const int* edst = eidx + ne;

    // ---- CSR build (by destination) ----
    zero_rowptr<<<(NNODES + 256) / 256, 256>>>();
    csr_hist<<<(ee + 255) / 256, 256>>>(edst, ne, ee);
    csr_scan<<<1, 1024>>>();
    csr_copy_fill<<<(NNODES + 255) / 256, 256>>>();
    csr_scatter<<<(ee + 255) / 256, 256>>>(esrc, edst, ne, ee);

    // ---- layer 1 transforms ----
    {
        dim3 grid((C1 + 63) / 64, (n + 63) / 64);
        sgemm_bias<<<grid, 256>>>(x, -1, W1l, b1l, /*cId=*/0, n, IN_CH, C1);
        sgemm_bias<<<grid, 256>>>(x, -1, W1r, b1r, /*cId=*/1, n, IN_CH, C1);
    }

    // ---- layer 1 fused edge pass (softmax+agg+bias+BN+ELU) ----
    gat1_fused<<<(NNODES * 32 + 255) / 256, 256>>>(att1, bias1, bn1_g, bn1_b, bn1_m, bn1_v);

    // ---- layer 2 transforms (read g_h1) ----
    {
        dim3 grid((HID + 63) / 64, (n + 63) / 64);
        sgemm_bias<<<grid, 256>>>(nullptr, /*aId=*/2, W2l, b2l, /*cId=*/3, n, C1, HID);
        sgemm_bias<<<grid, 256>>>(nullptr, /*aId=*/2, W2r, b2r, /*cId=*/4, n, C1, HID);
    }

    // ---- layer 2 fused edge pass ----
    gat2_fused<<<(NNODES * 32 + 255) / 256, 256>>>(att2, bias2, bn2_g, bn2_b, bn2_m, bn2_v);

    // ---- classifier ----
    classifier<<<(NNODES * 32 + 255) / 256, 256>>>(Wc, bc, out);
}

// round 14
// speedup vs baseline: 2.2876x; 2.2876x over previous
#include <cuda_runtime.h>
#include <math.h>

// ---------------- problem constants (fixed shapes) ----------------
#define NNODES 50000
#define NEDGES 800000
#define IN_CH  256
#define HID    64
#define HEADS  2
#define C1     (HEADS * HID)        // 128
#define EE     (NEDGES + NNODES)    // 850000 edges incl. self loops
#define NEG_SLOPE 0.2f
#define BN_EPS    1e-5f

// ---------------- scratch (device globals; no allocations) ----------------
__device__ __align__(16) float g_xl1[NNODES * C1];
__device__ __align__(16) float g_xr1[NNODES * C1];
__device__ __align__(16) float g_h1 [NNODES * C1];
__device__ __align__(16) float g_xl2[NNODES * HID];
__device__ __align__(16) float g_xr2[NNODES * HID];
__device__ int   g_rowptr[NNODES + 1];
__device__ int   g_fill[NNODES];
__device__ int   g_eid[EE];

// ---------------- CSR build ----------------
__global__ void zero_rowptr() {
    int i = blockIdx.x * blockDim.x + threadIdx.x;
    if (i <= NNODES) g_rowptr[i] = 0;
}

__global__ void csr_hist(const int* __restrict__ edst, int ne, int ee) {
    int e = blockIdx.x * blockDim.x + threadIdx.x;
    if (e >= ee) return;
    int d = (e < ne) ? edst[e] : (e - ne);
    atomicAdd(&g_rowptr[d + 1], 1);
}

// single-block inclusive scan over NNODES+1 counts (rowptr[0]=0 preserved)
__global__ void csr_scan() {
    __shared__ int warpsums[32];
    __shared__ int carry;
    int tid = threadIdx.x;              // 1024 threads
    int lane = tid & 31, wid = tid >> 5;
    if (tid == 0) carry = 0;
    __syncthreads();
    for (int base = 0; base <= NNODES; base += 1024) {
        int idx = base + tid;
        int v = (idx <= NNODES) ? g_rowptr[idx] : 0;
        int x = v;
        #pragma unroll
        for (int o = 1; o < 32; o <<= 1) {
            int y = __shfl_up_sync(0xFFFFFFFFu, x, o);
            if (lane >= o) x += y;
        }
        if (lane == 31) warpsums[wid] = x;
        __syncthreads();
        if (wid == 0) {
            int w = warpsums[lane];
            #pragma unroll
            for (int o = 1; o < 32; o <<= 1) {
                int y = __shfl_up_sync(0xFFFFFFFFu, w, o);
                if (lane >= o) w += y;
            }
            warpsums[lane] = w;
        }
        __syncthreads();
        int incl = x + (wid > 0 ? warpsums[wid - 1] : 0) + carry;
        if (idx <= NNODES) g_rowptr[idx] = incl;
        __syncthreads();
        if (tid == 1023) carry = incl;
        __syncthreads();
    }
}

__global__ void csr_copy_fill() {
    int i = blockIdx.x * blockDim.x + threadIdx.x;
    if (i < NNODES) g_fill[i] = g_rowptr[i];
}

__global__ void csr_scatter(const int* __restrict__ esrc, const int* __restrict__ edst,
                            int ne, int ee) {
    int e = blockIdx.x * blockDim.x + threadIdx.x;
    if (e >= ee) return;
    int s, d;
    if (e < ne) { s = esrc[e]; d = edst[e]; }
    else        { s = e - ne; d = s; }
    int pos = atomicAdd(&g_fill[d], 1);
    g_eid[pos] = s;
}

// ---------------- dual-output tiled SGEMM ----------------
// Cout0[:, 0:Nhalf] = A@B0 + bias0 ; Cout1[:, 0:Nhalf] = A@B1 + bias1
// column space is [0, 2*Nhalf); cols < Nhalf come from B0 -> Cout0, rest from B1 -> Cout1.
// Block tile 128x128, 256 threads, 8x8 per thread, BK=16, float4 I/O,
// software-pipelined global->reg prefetch.
#define BM 128
#define BN 128
#define BK 16

__device__ __forceinline__ float* scr(int id) {
    switch (id) {
        case 0: return g_xl1;
        case 1: return g_xr1;
        case 2: return g_h1;
        case 3: return g_xl2;
        case 4: return g_xr2;
    }
    return nullptr;
}

__global__ void __launch_bounds__(256, 2)
sgemm_dual(const float* __restrict__ Aext, int aId,
           const float* __restrict__ B0, const float* __restrict__ B1,
           const float* __restrict__ bias0, const float* __restrict__ bias1,
           int c0Id, int c1Id, int M, int K, int Nhalf) {
    const float* A = (aId >= 0) ? scr(aId) : Aext;
    float* Cout0 = scr(c0Id);
    float* Cout1 = scr(c1Id);

    __shared__ float As[BK][BM + 4];
    __shared__ float Bs[BK][BN];

    int tid = threadIdx.x;
    int tx = tid & 15, ty = tid >> 4;       // 16x16 thread grid, 8x8 each
    int rowBase = blockIdx.y * BM;
    int colBase = blockIdx.x * BN;

    // A load mapping: i in {tid, tid+256}; row = i>>2, kq = i&3 (float4 along K)
    // B load mapping: i in {tid, tid+256}; k = i>>5, cq = i&31 (float4 along N)
    float4 aReg[2], bReg[2];

    int nT = K / BK;

    // ---- prefetch tile 0 ----
    {
        int k0 = 0;
        #pragma unroll
        for (int u = 0; u < 2; u++) {
            int i = tid + u * 256;
            int ar = i >> 2, akq = i & 3;
            int grow = rowBase + ar;
            aReg[u] = (grow < M) ? *(const float4*)(A + (size_t)grow * K + k0 + akq * 4)
                                 : make_float4(0.f, 0.f, 0.f, 0.f);
            int bk = i >> 5, bcq = i & 31;
            int gcol = colBase + bcq * 4;
            const float* Bp = (gcol < Nhalf) ? (B0 + (size_t)(k0 + bk) * Nhalf + gcol)
                                             : (B1 + (size_t)(k0 + bk) * Nhalf + (gcol - Nhalf));
            bReg[u] = *(const float4*)Bp;
        }
    }

    float acc[8][8] = {};

    for (int t = 0; t < nT; t++) {
        // store prefetched tile to smem
        #pragma unroll
        for (int u = 0; u < 2; u++) {
            int i = tid + u * 256;
            int ar = i >> 2, akq = i & 3;
            As[akq * 4 + 0][ar] = aReg[u].x;
            As[akq * 4 + 1][ar] = aReg[u].y;
            As[akq * 4 + 2][ar] = aReg[u].z;
            As[akq * 4 + 3][ar] = aReg[u].w;
            int bk = i >> 5, bcq = i & 31;
            *(float4*)&Bs[bk][bcq * 4] = bReg[u];
        }
        __syncthreads();

        // prefetch next tile
        if (t + 1 < nT) {
            int k0 = (t + 1) * BK;
            #pragma unroll
            for (int u = 0; u < 2; u++) {
                int i = tid + u * 256;
                int ar = i >> 2, akq = i & 3;
                int grow = rowBase + ar;
                aReg[u] = (grow < M) ? *(const float4*)(A + (size_t)grow * K + k0 + akq * 4)
                                     : make_float4(0.f, 0.f, 0.f, 0.f);
                int bk = i >> 5, bcq = i & 31;
                int gcol = colBase + bcq * 4;
                const float* Bp = (gcol < Nhalf) ? (B0 + (size_t)(k0 + bk) * Nhalf + gcol)
                                                 : (B1 + (size_t)(k0 + bk) * Nhalf + (gcol - Nhalf));
                bReg[u] = *(const float4*)Bp;
            }
        }

        // compute
        #pragma unroll
        for (int kk = 0; kk < BK; kk++) {
            float4 a0 = *(const float4*)&As[kk][ty * 8];
            float4 a1 = *(const float4*)&As[kk][ty * 8 + 4];
            float4 b0 = *(const float4*)&Bs[kk][tx * 8];
            float4 b1 = *(const float4*)&Bs[kk][tx * 8 + 4];
            float a[8] = {a0.x, a0.y, a0.z, a0.w, a1.x, a1.y, a1.z, a1.w};
            float b[8] = {b0.x, b0.y, b0.z, b0.w, b1.x, b1.y, b1.z, b1.w};
            #pragma unroll
            for (int i = 0; i < 8; i++)
                #pragma unroll
                for (int j = 0; j < 8; j++) acc[i][j] += a[i] * b[j];
        }
        __syncthreads();
    }

    // ---- epilogue: bias + store (8 cols per thread stay within one half; Nhalf % 8 == 0) ----
    int gcol = colBase + tx * 8;
    int half = (gcol >= Nhalf);
    float* Cw = half ? Cout1 : Cout0;
    const float* bias = half ? bias1 : bias0;
    int lcol = half ? (gcol - Nhalf) : gcol;
    float4 bi0 = *(const float4*)(bias + lcol);
    float4 bi1 = *(const float4*)(bias + lcol + 4);

    #pragma unroll
    for (int i = 0; i < 8; i++) {
        int grow = rowBase + ty * 8 + i;
        if (grow >= M) continue;
        float4 o0 = make_float4(acc[i][0] + bi0.x, acc[i][1] + bi0.y,
                                acc[i][2] + bi0.z, acc[i][3] + bi0.w);
        float4 o1 = make_float4(acc[i][4] + bi1.x, acc[i][5] + bi1.y,
                                acc[i][6] + bi1.z, acc[i][7] + bi1.w);
        *(float4*)(Cw + (size_t)grow * Nhalf + lcol)     = o0;
        *(float4*)(Cw + (size_t)grow * Nhalf + lcol + 4) = o1;
    }
}

// ---------------- layer 1 fused: online softmax + aggregation + bias + BN + ELU ----
// one warp per destination node; lane covers channels [4*lane, 4*lane+4)
// lanes 0-15 -> head 0 (ch 0..63), lanes 16-31 -> head 1 (ch 64..127)
__global__ void gat1_fused(const float* __restrict__ att, const float* __restrict__ bias,
                           const float* __restrict__ bng, const float* __restrict__ bnb,
                           const float* __restrict__ bnm, const float* __restrict__ bnv) {
    int warp = (blockIdx.x * blockDim.x + threadIdx.x) >> 5;
    int lane = threadIdx.x & 31;
    if (warp >= NNODES) return;
    int d = warp;
    int cbase = lane * 4;

    float4 xr = *(const float4*)(g_xr1 + (size_t)d * C1 + cbase);
    float4 a4 = *(const float4*)(att + cbase);

    float4 acc = make_float4(0.f, 0.f, 0.f, 0.f);
    float m = -INFINITY, s = 0.f;

    int start = g_rowptr[d], end = g_rowptr[d + 1];
    for (int base = start; base < end; base += 32) {
        int sv = (base + lane < end) ? g_eid[base + lane] : 0;
        int nb = min(32, end - base);
        for (int j = 0; j < nb; j++) {
            int src = __shfl_sync(0xFFFFFFFFu, sv, j);
            float4 xl = *(const float4*)(g_xl1 + (size_t)src * C1 + cbase);
            float v0 = xl.x + xr.x; v0 = v0 > 0.f ? v0 : NEG_SLOPE * v0;
            float v1 = xl.y + xr.y; v1 = v1 > 0.f ? v1 : NEG_SLOPE * v1;
            float v2 = xl.z + xr.z; v2 = v2 > 0.f ? v2 : NEG_SLOPE * v2;
            float v3 = xl.w + xr.w; v3 = v3 > 0.f ? v3 : NEG_SLOPE * v3;
            float t = a4.x * v0 + a4.y * v1 + a4.z * v2 + a4.w * v3;
            // butterfly reduce within each 16-lane half (per-head logit)
            t += __shfl_xor_sync(0xFFFFFFFFu, t, 8);
            t += __shfl_xor_sync(0xFFFFFFFFu, t, 4);
            t += __shfl_xor_sync(0xFFFFFFFFu, t, 2);
            t += __shfl_xor_sync(0xFFFFFFFFu, t, 1);
            // online softmax update (per-head state, uniform within half-warp)
            float mn = fmaxf(m, t);
            float sc = __expf(m - mn);   // 0 on first edge (m = -inf)
            float p  = __expf(t - mn);
            s = s * sc + p;
            acc.x = acc.x * sc + p * xl.x;
            acc.y = acc.y * sc + p * xl.y;
            acc.z = acc.z * sc + p * xl.z;
            acc.w = acc.w * sc + p * xl.w;
            m = mn;
        }
    }

    float inv = 1.f / s;
    float4 bi = *(const float4*)(bias + cbase);
    float4 gg = *(const float4*)(bng + cbase);
    float4 bb = *(const float4*)(bnb + cbase);
    float4 mm = *(const float4*)(bnm + cbase);
    float4 vv = *(const float4*)(bnv + cbase);
    float4 o;
    o.x = (acc.x * inv + bi.x - mm.x) * rsqrtf(vv.x + BN_EPS) * gg.x + bb.x;
    o.y = (acc.y * inv + bi.y - mm.y) * rsqrtf(vv.y + BN_EPS) * gg.y + bb.y;
    o.z = (acc.z * inv + bi.z - mm.z) * rsqrtf(vv.z + BN_EPS) * gg.z + bb.z;
    o.w = (acc.w * inv + bi.w - mm.w) * rsqrtf(vv.w + BN_EPS) * gg.w + bb.w;
    o.x = o.x > 0.f ? o.x : __expf(o.x) - 1.f;
    o.y = o.y > 0.f ? o.y : __expf(o.y) - 1.f;
    o.z = o.z > 0.f ? o.z : __expf(o.z) - 1.f;
    o.w = o.w > 0.f ? o.w : __expf(o.w) - 1.f;
    *(float4*)(g_h1 + (size_t)d * C1 + cbase) = o;
}

// ---------------- layer 2 fused: 64 ch, 1 head; lane covers 2 channels ----------------
// classifier fused: out[d] = sigmoid(h2[d,:] . Wc + bc); g_h2 never materialized
__global__ void gat2_fused(const float* __restrict__ att, const float* __restrict__ bias,
                           const float* __restrict__ bng, const float* __restrict__ bnb,
                           const float* __restrict__ bnm, const float* __restrict__ bnv,
                           const float* __restrict__ Wc, const float* __restrict__ bc,
                           float* __restrict__ out) {
    int warp = (blockIdx.x * blockDim.x + threadIdx.x) >> 5;
    int lane = threadIdx.x & 31;
    if (warp >= NNODES) return;
    int d = warp;
    int cbase = lane * 2;

    float2 xr = *(const float2*)(g_xr2 + (size_t)d * HID + cbase);
    float2 a2 = *(const float2*)(att + cbase);

    float2 acc = make_float2(0.f, 0.f);
    float m = -INFINITY, s = 0.f;

    int start = g_rowptr[d], end = g_rowptr[d + 1];
    for (int base = start; base < end; base += 32) {
        int sv = (base + lane < end) ? g_eid[base + lane] : 0;
        int nb = min(32, end - base);
        for (int j = 0; j < nb; j++) {
            int src = __shfl_sync(0xFFFFFFFFu, sv, j);
            float2 xl = *(const float2*)(g_xl2 + (size_t)src * HID + cbase);
            float v0 = xl.x + xr.x; v0 = v0 > 0.f ? v0 : NEG_SLOPE * v0;
            float v1 = xl.y + xr.y; v1 = v1 > 0.f ? v1 : NEG_SLOPE * v1;
            float t = a2.x * v0 + a2.y * v1;
            #pragma unroll
            for (int o = 16; o; o >>= 1) t += __shfl_xor_sync(0xFFFFFFFFu, t, o);
            float mn = fmaxf(m, t);
            float sc = __expf(m - mn);
            float p  = __expf(t - mn);
            s = s * sc + p;
            acc.x = acc.x * sc + p * xl.x;
            acc.y = acc.y * sc + p * xl.y;
            m = mn;
        }
    }

    float inv = 1.f / s;
    float2 bi = *(const float2*)(bias + cbase);
    float2 gg = *(const float2*)(bng + cbase);
    float2 bb = *(const float2*)(bnb + cbase);
    float2 mm = *(const float2*)(bnm + cbase);
    float2 vv = *(const float2*)(bnv + cbase);
    float2 o;
    o.x = (acc.x * inv + bi.x - mm.x) * rsqrtf(vv.x + BN_EPS) * gg.x + bb.x;
    o.y = (acc.y * inv + bi.y - mm.y) * rsqrtf(vv.y + BN_EPS) * gg.y + bb.y;
    o.x = o.x > 0.f ? o.x : __expf(o.x) - 1.f;
    o.y = o.y > 0.f ? o.y : __expf(o.y) - 1.f;

    // fused classifier
    float cls = o.x * Wc[cbase] + o.y * Wc[cbase + 1];
    #pragma unroll
    for (int off = 16; off; off >>= 1) cls += __shfl_xor_sync(0xFFFFFFFFu, cls, off);
    if (lane == 0) out[d] = 1.f / (1.f + __expf(-(cls + bc[0])));
}

// ---------------- host launcher ----------------
extern "C" void kernel_launch(void* const* d_in, const int* in_sizes, int n_in,
                              void* d_out, int out_size) {
    const float* x      = (const float*)d_in[0];
    const int*   eidx   = (const int*)d_in[1];
    const float* W1l    = (const float*)d_in[2];
    const float* b1l    = (const float*)d_in[3];
    const float* W1r    = (const float*)d_in[4];
    const float* b1r    = (const float*)d_in[5];
    const float* att1   = (const float*)d_in[6];
    const float* bias1  = (const float*)d_in[7];
    const float* bn1_g  = (const float*)d_in[8];
    const float* bn1_b  = (const float*)d_in[9];
    const float* bn1_m  = (const float*)d_in[10];
    const float* bn1_v  = (const float*)d_in[11];
    const float* W2l    = (const float*)d_in[12];
    const float* b2l    = (const float*)d_in[13];
    const float* W2r    = (const float*)d_in[14];
    const float* b2r    = (const float*)d_in[15];
    const float* att2   = (const float*)d_in[16];
    const float* bias2  = (const float*)d_in[17];
    const float* bn2_g  = (const float*)d_in[18];
    const float* bn2_b  = (const float*)d_in[19];
    const float* bn2_m  = (const float*)d_in[20];
    const float* bn2_v  = (const float*)d_in[21];
    const float* Wc     = (const float*)d_in[22];
    const float* bc     = (const float*)d_in[23];
    float* out = (float*)d_out;

    const int n  = in_sizes[0] / IN_CH;    // 50000
    const int ne = in_sizes[1] / 2;        // 800000
    const int ee = ne + n;                 // 850000
    const int* esrc = eidx;
    const int* edst = eidx + ne;

    // ---- CSR build (by destination) ----
    zero_rowptr<<<(NNODES + 256) / 256, 256>>>();
    csr_hist<<<(ee + 255) / 256, 256>>>(edst, ne, ee);
    csr_scan<<<1, 1024>>>();
    csr_copy_fill<<<(NNODES + 255) / 256, 256>>>();
    csr_scatter<<<(ee + 255) / 256, 256>>>(esrc, edst, ne, ee);

    // ---- layer 1 transforms: xl1 = x@W1l+b1l, xr1 = x@W1r+b1r (one launch) ----
    {
        dim3 grid(2 * C1 / BN, (n + BM - 1) / BM);      // (2, 391)
        sgemm_dual<<<grid, 256>>>(x, -1, W1l, W1r, b1l, b1r,
                                  /*c0=*/0, /*c1=*/1, n, IN_CH, C1);
    }

    // ---- layer 1 fused edge pass (softmax+agg+bias+BN+ELU) ----
    gat1_fused<<<(NNODES * 32 + 255) / 256, 256>>>(att1, bias1, bn1_g, bn1_b, bn1_m, bn1_v);

    // ---- layer 2 transforms: xl2 = h1@W2l+b2l, xr2 = h1@W2r+b2r (one launch) ----
    {
        dim3 grid(2 * HID / BN, (n + BM - 1) / BM);     // (1, 391)
        sgemm_dual<<<grid, 256>>>(nullptr, /*aId=*/2, W2l, W2r, b2l, b2r,
                                  /*c0=*/3, /*c1=*/4, n, C1, HID);
    }

    // ---- layer 2 fused edge pass + classifier ----
    gat2_fused<<<(NNODES * 32 + 255) / 256, 256>>>(att2, bias2, bn2_g, bn2_b, bn2_m, bn2_v,
                                                   Wc, bc, out);
}

// round 15
// speedup vs baseline: 2.3600x; 1.0316x over previous
#include <cuda_runtime.h>
#include <math.h>

// ---------------- problem constants (fixed shapes) ----------------
#define NNODES 50000
#define NEDGES 800000
#define IN_CH  256
#define HID    64
#define HEADS  2
#define C1     (HEADS * HID)        // 128
#define EE     (NEDGES + NNODES)    // 850000 edges incl. self loops
#define NEG_SLOPE 0.2f
#define BN_EPS    1e-5f

// ---------------- scratch (device globals; no allocations) ----------------
__device__ __align__(16) float g_xl1[NNODES * C1];
__device__ __align__(16) float g_xr1[NNODES * C1];
__device__ __align__(16) float g_h1 [NNODES * C1];
__device__ __align__(16) float g_xl2[NNODES * HID];
__device__ __align__(16) float g_xr2[NNODES * HID];
__device__ int   g_rowptr[NNODES + 1];
__device__ int   g_fill[NNODES];
__device__ int   g_eid[EE];

// ---------------- CSR build ----------------
__global__ void zero_rowptr() {
    int i = blockIdx.x * blockDim.x + threadIdx.x;
    if (i <= NNODES) g_rowptr[i] = 0;
}

__global__ void csr_hist(const int* __restrict__ edst, int ne, int ee) {
    int e = blockIdx.x * blockDim.x + threadIdx.x;
    if (e >= ee) return;
    int d = (e < ne) ? edst[e] : (e - ne);
    atomicAdd(&g_rowptr[d + 1], 1);
}

// single-block inclusive scan over NNODES+1 counts (rowptr[0]=0 preserved)
__global__ void csr_scan() {
    __shared__ int warpsums[32];
    __shared__ int carry;
    int tid = threadIdx.x;              // 1024 threads
    int lane = tid & 31, wid = tid >> 5;
    if (tid == 0) carry = 0;
    __syncthreads();
    for (int base = 0; base <= NNODES; base += 1024) {
        int idx = base + tid;
        int v = (idx <= NNODES) ? g_rowptr[idx] : 0;
        int x = v;
        #pragma unroll
        for (int o = 1; o < 32; o <<= 1) {
            int y = __shfl_up_sync(0xFFFFFFFFu, x, o);
            if (lane >= o) x += y;
        }
        if (lane == 31) warpsums[wid] = x;
        __syncthreads();
        if (wid == 0) {
            int w = warpsums[lane];
            #pragma unroll
            for (int o = 1; o < 32; o <<= 1) {
                int y = __shfl_up_sync(0xFFFFFFFFu, w, o);
                if (lane >= o) w += y;
            }
            warpsums[lane] = w;
        }
        __syncthreads();
        int incl = x + (wid > 0 ? warpsums[wid - 1] : 0) + carry;
        if (idx <= NNODES) g_rowptr[idx] = incl;
        __syncthreads();
        if (tid == 1023) carry = incl;
        __syncthreads();
    }
}

__global__ void csr_copy_fill() {
    int i = blockIdx.x * blockDim.x + threadIdx.x;
    if (i < NNODES) g_fill[i] = g_rowptr[i];
}

__global__ void csr_scatter(const int* __restrict__ esrc, const int* __restrict__ edst,
                            int ne, int ee) {
    int e = blockIdx.x * blockDim.x + threadIdx.x;
    if (e >= ee) return;
    int s, d;
    if (e < ne) { s = esrc[e]; d = edst[e]; }
    else        { s = e - ne; d = s; }
    int pos = atomicAdd(&g_fill[d], 1);
    g_eid[pos] = s;
}

// ---------------- scratch-id indirection ----------------
__device__ __forceinline__ float* scr(int id) {
    switch (id) {
        case 0: return g_xl1;
        case 1: return g_xr1;
        case 2: return g_h1;
        case 3: return g_xl2;
        case 4: return g_xr2;
    }
    return nullptr;
}

// ---------------- TF32 tensor-core dual GEMM (3xTF32 precision split) ----------------
// Cout0[:, 0:Nhalf] = A@B0 + bias0 ; Cout1[:, 0:Nhalf] = A@B1 + bias1
// column space [0, 2*Nhalf): cols < Nhalf -> B0/Cout0, else B1/Cout1.
// Block 128x128, BK=16, 256 threads = 8 warps (4 row x 2 col), warp tile 32x64,
// mma.sync.m16n8k8 tf32 with hi/lo split: D += Ahi*Bhi + Ahi*Blo + Alo*Bhi.
#define TBM 128
#define TBN 128
#define TBK 16

__device__ __forceinline__ unsigned cvt_tf32(float x) {
    unsigned r; asm("cvt.rna.tf32.f32 %0, %1;" : "=r"(r) : "f"(x)); return r;
}

__device__ __forceinline__ void mma8(float* c, const unsigned* a, unsigned b0, unsigned b1) {
    asm volatile("mma.sync.aligned.m16n8k8.row.col.f32.tf32.tf32.f32 "
        "{%0,%1,%2,%3}, {%4,%5,%6,%7}, {%8,%9}, {%0,%1,%2,%3};\n"
        : "+f"(c[0]), "+f"(c[1]), "+f"(c[2]), "+f"(c[3])
        : "r"(a[0]), "r"(a[1]), "r"(a[2]), "r"(a[3]), "r"(b0), "r"(b1));
}

__global__ void __launch_bounds__(256)
gemm_tf32_dual(const float* __restrict__ Aext, int aId,
               const float* __restrict__ B0, const float* __restrict__ B1,
               const float* __restrict__ bias0, const float* __restrict__ bias1,
               int c0Id, int c1Id, int M, int K, int Nhalf) {
    const float* A = (aId >= 0) ? scr(aId) : Aext;
    float* Cout0 = scr(c0Id);
    float* Cout1 = scr(c1Id);

    // As: [m][k] layout, pad 4 -> conflict-free fragment reads ((20m+k)%32 distinct)
    // Bs: [k][n] layout, pad 8 -> conflict-free fragment reads ((8k+n)%32 distinct)
    __shared__ unsigned AsHi[TBM][TBK + 4], AsLo[TBM][TBK + 4];
    __shared__ unsigned BsHi[TBK][TBN + 8], BsLo[TBK][TBN + 8];

    int tid = threadIdx.x;
    int lane = tid & 31, w = tid >> 5;
    int gid = lane >> 2, tig = lane & 3;
    int wr = w >> 1, wc = w & 1;            // 4x2 warp grid
    int WR = wr * 32, WC = wc * 64;
    int rowBase = blockIdx.y * TBM;
    int colBase = blockIdx.x * TBN;

    // load mappings (2 float4 per thread for A and for B per tile)
    int aRow[2], aKq[2], bK[2], bCq[2];
    #pragma unroll
    for (int u = 0; u < 2; u++) {
        int i = tid + u * 256;
        aRow[u] = i >> 2;  aKq[u] = i & 3;    // 128 rows x 4 k-quads
        bK[u]  = i >> 5;   bCq[u] = i & 31;   // 16 k x 32 col-quads
    }

    float4 aPre[2], bPre[2];
    const float4 zero4 = make_float4(0.f, 0.f, 0.f, 0.f);

    int nT = K / TBK;

    // prefetch tile 0
    #pragma unroll
    for (int u = 0; u < 2; u++) {
        int grow = rowBase + aRow[u];
        aPre[u] = (grow < M) ? *(const float4*)(A + (size_t)grow * K + aKq[u] * 4) : zero4;
        int gcol = colBase + bCq[u] * 4;
        const float* Bp = (gcol < Nhalf) ? (B0 + (size_t)bK[u] * Nhalf + gcol)
                                         : (B1 + (size_t)bK[u] * Nhalf + (gcol - Nhalf));
        bPre[u] = *(const float4*)Bp;
    }

    float acc[2][8][4];
    #pragma unroll
    for (int i = 0; i < 2; i++)
        #pragma unroll
        for (int j = 0; j < 8; j++)
            #pragma unroll
            for (int q = 0; q < 4; q++) acc[i][j][q] = 0.f;

    for (int t = 0; t < nT; t++) {
        // split + store prefetched tile to smem
        #pragma unroll
        for (int u = 0; u < 2; u++) {
            float av[4] = {aPre[u].x, aPre[u].y, aPre[u].z, aPre[u].w};
            #pragma unroll
            for (int j = 0; j < 4; j++) {
                unsigned h = cvt_tf32(av[j]);
                float lf = av[j] - __uint_as_float(h);
                AsHi[aRow[u]][aKq[u] * 4 + j] = h;
                AsLo[aRow[u]][aKq[u] * 4 + j] = cvt_tf32(lf);
            }
            float bv[4] = {bPre[u].x, bPre[u].y, bPre[u].z, bPre[u].w};
            #pragma unroll
            for (int j = 0; j < 4; j++) {
                unsigned h = cvt_tf32(bv[j]);
                float lf = bv[j] - __uint_as_float(h);
                BsHi[bK[u]][bCq[u] * 4 + j] = h;
                BsLo[bK[u]][bCq[u] * 4 + j] = cvt_tf32(lf);
            }
        }
        __syncthreads();

        // prefetch next tile
        if (t + 1 < nT) {
            int k0 = (t + 1) * TBK;
            #pragma unroll
            for (int u = 0; u < 2; u++) {
                int grow = rowBase + aRow[u];
                aPre[u] = (grow < M) ? *(const float4*)(A + (size_t)grow * K + k0 + aKq[u] * 4)
                                     : zero4;
                int gcol = colBase + bCq[u] * 4;
                const float* Bp = (gcol < Nhalf) ? (B0 + (size_t)(k0 + bK[u]) * Nhalf + gcol)
                                                 : (B1 + (size_t)(k0 + bK[u]) * Nhalf + (gcol - Nhalf));
                bPre[u] = *(const float4*)Bp;
            }
        }

        // compute: 2 k-chunks of 8
        #pragma unroll
        for (int kc = 0; kc < 2; kc++) {
            int kb = kc * 8 + tig;
            unsigned ahi[2][4], alo[2][4];
            #pragma unroll
            for (int ti = 0; ti < 2; ti++) {
                int r = WR + ti * 16 + gid;
                ahi[ti][0] = AsHi[r][kb];       ahi[ti][1] = AsHi[r + 8][kb];
                ahi[ti][2] = AsHi[r][kb + 4];   ahi[ti][3] = AsHi[r + 8][kb + 4];
                alo[ti][0] = AsLo[r][kb];       alo[ti][1] = AsLo[r + 8][kb];
                alo[ti][2] = AsLo[r][kb + 4];   alo[ti][3] = AsLo[r + 8][kb + 4];
            }
            #pragma unroll
            for (int tj = 0; tj < 8; tj++) {
                int n = WC + tj * 8 + gid;
                unsigned bh0 = BsHi[kb][n], bh1 = BsHi[kb + 4][n];
                unsigned bl0 = BsLo[kb][n], bl1 = BsLo[kb + 4][n];
                #pragma unroll
                for (int ti = 0; ti < 2; ti++) {
                    mma8(acc[ti][tj], ahi[ti], bh0, bh1);
                    mma8(acc[ti][tj], ahi[ti], bl0, bl1);
                    mma8(acc[ti][tj], alo[ti], bh0, bh1);
                }
            }
        }
        __syncthreads();
    }

    // ---- epilogue: bias + store (float2 per row per col-tile) ----
    #pragma unroll
    for (int tj = 0; tj < 8; tj++) {
        int gcol = colBase + WC + tj * 8 + tig * 2;
        int half = (gcol >= Nhalf);
        float* Cw = half ? Cout1 : Cout0;
        const float* bias = half ? bias1 : bias0;
        int lcol = half ? (gcol - Nhalf) : gcol;
        float2 bi = *(const float2*)(bias + lcol);
        #pragma unroll
        for (int ti = 0; ti < 2; ti++) {
            int r0 = rowBase + WR + ti * 16 + gid;
            if (r0 < M) {
                float2 o = make_float2(acc[ti][tj][0] + bi.x, acc[ti][tj][1] + bi.y);
                *(float2*)(Cw + (size_t)r0 * Nhalf + lcol) = o;
            }
            int r1 = r0 + 8;
            if (r1 < M) {
                float2 o = make_float2(acc[ti][tj][2] + bi.x, acc[ti][tj][3] + bi.y);
                *(float2*)(Cw + (size_t)r1 * Nhalf + lcol) = o;
            }
        }
    }
}

// ---------------- layer 1 fused: online softmax + aggregation + bias + BN + ELU ----
// one warp per destination node; lane covers channels [4*lane, 4*lane+4)
// lanes 0-15 -> head 0 (ch 0..63), lanes 16-31 -> head 1 (ch 64..127)
__global__ void gat1_fused(const float* __restrict__ att, const float* __restrict__ bias,
                           const float* __restrict__ bng, const float* __restrict__ bnb,
                           const float* __restrict__ bnm, const float* __restrict__ bnv) {
    int warp = (blockIdx.x * blockDim.x + threadIdx.x) >> 5;
    int lane = threadIdx.x & 31;
    if (warp >= NNODES) return;
    int d = warp;
    int cbase = lane * 4;

    float4 xr = *(const float4*)(g_xr1 + (size_t)d * C1 + cbase);
    float4 a4 = *(const float4*)(att + cbase);

    float4 acc = make_float4(0.f, 0.f, 0.f, 0.f);
    float m = -INFINITY, s = 0.f;

    int start = g_rowptr[d], end = g_rowptr[d + 1];
    for (int base = start; base < end; base += 32) {
        int sv = (base + lane < end) ? g_eid[base + lane] : 0;
        int nb = min(32, end - base);
        for (int j = 0; j < nb; j++) {
            int src = __shfl_sync(0xFFFFFFFFu, sv, j);
            float4 xl = *(const float4*)(g_xl1 + (size_t)src * C1 + cbase);
            float v0 = xl.x + xr.x; v0 = v0 > 0.f ? v0 : NEG_SLOPE * v0;
            float v1 = xl.y + xr.y; v1 = v1 > 0.f ? v1 : NEG_SLOPE * v1;
            float v2 = xl.z + xr.z; v2 = v2 > 0.f ? v2 : NEG_SLOPE * v2;
            float v3 = xl.w + xr.w; v3 = v3 > 0.f ? v3 : NEG_SLOPE * v3;
            float t = a4.x * v0 + a4.y * v1 + a4.z * v2 + a4.w * v3;
            // butterfly reduce within each 16-lane half (per-head logit)
            t += __shfl_xor_sync(0xFFFFFFFFu, t, 8);
            t += __shfl_xor_sync(0xFFFFFFFFu, t, 4);
            t += __shfl_xor_sync(0xFFFFFFFFu, t, 2);
            t += __shfl_xor_sync(0xFFFFFFFFu, t, 1);
            // online softmax update (per-head state, uniform within half-warp)
            float mn = fmaxf(m, t);
            float sc = __expf(m - mn);   // 0 on first edge (m = -inf)
            float p  = __expf(t - mn);
            s = s * sc + p;
            acc.x = acc.x * sc + p * xl.x;
            acc.y = acc.y * sc + p * xl.y;
            acc.z = acc.z * sc + p * xl.z;
            acc.w = acc.w * sc + p * xl.w;
            m = mn;
        }
    }

    float inv = 1.f / s;
    float4 bi = *(const float4*)(bias + cbase);
    float4 gg = *(const float4*)(bng + cbase);
    float4 bb = *(const float4*)(bnb + cbase);
    float4 mm = *(const float4*)(bnm + cbase);
    float4 vv = *(const float4*)(bnv + cbase);
    float4 o;
    o.x = (acc.x * inv + bi.x - mm.x) * rsqrtf(vv.x + BN_EPS) * gg.x + bb.x;
    o.y = (acc.y * inv + bi.y - mm.y) * rsqrtf(vv.y + BN_EPS) * gg.y + bb.y;
    o.z = (acc.z * inv + bi.z - mm.z) * rsqrtf(vv.z + BN_EPS) * gg.z + bb.z;
    o.w = (acc.w * inv + bi.w - mm.w) * rsqrtf(vv.w + BN_EPS) * gg.w + bb.w;
    o.x = o.x > 0.f ? o.x : __expf(o.x) - 1.f;
    o.y = o.y > 0.f ? o.y : __expf(o.y) - 1.f;
    o.z = o.z > 0.f ? o.z : __expf(o.z) - 1.f;
    o.w = o.w > 0.f ? o.w : __expf(o.w) - 1.f;
    *(float4*)(g_h1 + (size_t)d * C1 + cbase) = o;
}

// ---------------- layer 2 fused: 64 ch, 1 head; classifier fused ----------------
__global__ void gat2_fused(const float* __restrict__ att, const float* __restrict__ bias,
                           const float* __restrict__ bng, const float* __restrict__ bnb,
                           const float* __restrict__ bnm, const float* __restrict__ bnv,
                           const float* __restrict__ Wc, const float* __restrict__ bc,
                           float* __restrict__ out) {
    int warp = (blockIdx.x * blockDim.x + threadIdx.x) >> 5;
    int lane = threadIdx.x & 31;
    if (warp >= NNODES) return;
    int d = warp;
    int cbase = lane * 2;

    float2 xr = *(const float2*)(g_xr2 + (size_t)d * HID + cbase);
    float2 a2 = *(const float2*)(att + cbase);

    float2 acc = make_float2(0.f, 0.f);
    float m = -INFINITY, s = 0.f;

    int start = g_rowptr[d], end = g_rowptr[d + 1];
    for (int base = start; base < end; base += 32) {
        int sv = (base + lane < end) ? g_eid[base + lane] : 0;
        int nb = min(32, end - base);
        for (int j = 0; j < nb; j++) {
            int src = __shfl_sync(0xFFFFFFFFu, sv, j);
            float2 xl = *(const float2*)(g_xl2 + (size_t)src * HID + cbase);
            float v0 = xl.x + xr.x; v0 = v0 > 0.f ? v0 : NEG_SLOPE * v0;
            float v1 = xl.y + xr.y; v1 = v1 > 0.f ? v1 : NEG_SLOPE * v1;
            float t = a2.x * v0 + a2.y * v1;
            #pragma unroll
            for (int o = 16; o; o >>= 1) t += __shfl_xor_sync(0xFFFFFFFFu, t, o);
            float mn = fmaxf(m, t);
            float sc = __expf(m - mn);
            float p  = __expf(t - mn);
            s = s * sc + p;
            acc.x = acc.x * sc + p * xl.x;
            acc.y = acc.y * sc + p * xl.y;
            m = mn;
        }
    }

    float inv = 1.f / s;
    float2 bi = *(const float2*)(bias + cbase);
    float2 gg = *(const float2*)(bng + cbase);
    float2 bb = *(const float2*)(bnb + cbase);
    float2 mm = *(const float2*)(bnm + cbase);
    float2 vv = *(const float2*)(bnv + cbase);
    float2 o;
    o.x = (acc.x * inv + bi.x - mm.x) * rsqrtf(vv.x + BN_EPS) * gg.x + bb.x;
    o.y = (acc.y * inv + bi.y - mm.y) * rsqrtf(vv.y + BN_EPS) * gg.y + bb.y;
    o.x = o.x > 0.f ? o.x : __expf(o.x) - 1.f;
    o.y = o.y > 0.f ? o.y : __expf(o.y) - 1.f;

    // fused classifier
    float cls = o.x * Wc[cbase] + o.y * Wc[cbase + 1];
    #pragma unroll
    for (int off = 16; off; off >>= 1) cls += __shfl_xor_sync(0xFFFFFFFFu, cls, off);
    if (lane == 0) out[d] = 1.f / (1.f + __expf(-(cls + bc[0])));
}

// ---------------- host launcher ----------------
extern "C" void kernel_launch(void* const* d_in, const int* in_sizes, int n_in,
                              void* d_out, int out_size) {
    const float* x      = (const float*)d_in[0];
    const int*   eidx   = (const int*)d_in[1];
    const float* W1l    = (const float*)d_in[2];
    const float* b1l    = (const float*)d_in[3];
    const float* W1r    = (const float*)d_in[4];
    const float* b1r    = (const float*)d_in[5];
    const float* att1   = (const float*)d_in[6];
    const float* bias1  = (const float*)d_in[7];
    const float* bn1_g  = (const float*)d_in[8];
    const float* bn1_b  = (const float*)d_in[9];
    const float* bn1_m  = (const float*)d_in[10];
    const float* bn1_v  = (const float*)d_in[11];
    const float* W2l    = (const float*)d_in[12];
    const float* b2l    = (const float*)d_in[13];
    const float* W2r    = (const float*)d_in[14];
    const float* b2r    = (const float*)d_in[15];
    const float* att2   = (const float*)d_in[16];
    const float* bias2  = (const float*)d_in[17];
    const float* bn2_g  = (const float*)d_in[18];
    const float* bn2_b  = (const float*)d_in[19];
    const float* bn2_m  = (const float*)d_in[20];
    const float* bn2_v  = (const float*)d_in[21];
    const float* Wc     = (const float*)d_in[22];
    const float* bc     = (const float*)d_in[23];
    float* out = (float*)d_out;

    const int n  = in_sizes[0] / IN_CH;    // 50000
    const int ne = in_sizes[1] / 2;        // 800000
    const int ee = ne + n;                 // 850000
    const int* esrc = eidx;
    const int* edst = eidx + ne;

    // one-time stream/event creation (host objects only, first call is the
    // non-captured correctness run, so nothing is created during capture)
    static cudaStream_t sCsr = nullptr;
    static cudaEvent_t evFork = nullptr, evJoin = nullptr;
    if (sCsr == nullptr) {
        cudaStreamCreateWithFlags(&sCsr, cudaStreamNonBlocking);
        cudaEventCreateWithFlags(&evFork, cudaEventDisableTiming);
        cudaEventCreateWithFlags(&evJoin, cudaEventDisableTiming);
    }

    // ---- fork: CSR build on side stream, concurrent with layer-1 GEMM ----
    cudaEventRecord(evFork, 0);
    cudaStreamWaitEvent(sCsr, evFork, 0);
    zero_rowptr<<<(NNODES + 256) / 256, 256, 0, sCsr>>>();
    csr_hist<<<(ee + 255) / 256, 256, 0, sCsr>>>(edst, ne, ee);
    csr_scan<<<1, 1024, 0, sCsr>>>();
    csr_copy_fill<<<(NNODES + 255) / 256, 256, 0, sCsr>>>();
    csr_scatter<<<(ee + 255) / 256, 256, 0, sCsr>>>(esrc, edst, ne, ee);
    cudaEventRecord(evJoin, sCsr);

    // ---- layer 1 transforms: xl1 = x@W1l+b1l, xr1 = x@W1r+b1r (tensor cores) ----
    {
        dim3 grid(2 * C1 / TBN, (n + TBM - 1) / TBM);   // (2, 391)
        gemm_tf32_dual<<<grid, 256>>>(x, -1, W1l, W1r, b1l, b1r,
                                      /*c0=*/0, /*c1=*/1, n, IN_CH, C1);
    }

    // ---- join: CSR ready before edge pass ----
    cudaStreamWaitEvent(0, evJoin, 0);

    // ---- layer 1 fused edge pass (softmax+agg+bias+BN+ELU) ----
    gat1_fused<<<(NNODES * 32 + 255) / 256, 256>>>(att1, bias1, bn1_g, bn1_b, bn1_m, bn1_v);

    // ---- layer 2 transforms: xl2 = h1@W2l+b2l, xr2 = h1@W2r+b2r ----
    {
        dim3 grid(2 * HID / TBN, (n + TBM - 1) / TBM);  // (1, 391)
        gemm_tf32_dual<<<grid, 256>>>(nullptr, /*aId=*/2, W2l, W2r, b2l, b2r,
                                      /*c0=*/3, /*c1=*/4, n, C1, HID);
    }

    // ---- layer 2 fused edge pass + classifier ----
    gat2_fused<<<(NNODES * 32 + 255) / 256, 256>>>(att2, bias2, bn2_g, bn2_b, bn2_m, bn2_v,
                                                   Wc, bc, out);
}